// round 1
// baseline (speedup 1.0000x reference)
#include <cuda_runtime.h>
#include <math.h>

#define N_NODES 8192
#define F_IN 256
#define F_OUT 128
#define ALPHA 0.2f
#define ROWS_PER_BLK 32
#define MAXNZ 1024

// Scratch (no allocations allowed)
__device__ float g_h[N_NODES * F_OUT];   // 4 MB
__device__ float g_e1[N_NODES];
__device__ float g_e2[N_NODES];

// ---------------------------------------------------------------------------
// K1: h = x @ W  (and fused e1 = h@a1, e2 = h@a2)
// grid = 256 blocks, 256 threads, dyn smem = W(128KB) + x tile(32KB)
// Thread tile: 4 rows x 4 cols.
// ---------------------------------------------------------------------------
__global__ void __launch_bounds__(256, 1)
gat_k1(const float* __restrict__ x, const float* __restrict__ W,
       const float* __restrict__ a)
{
    extern __shared__ float sm[];
    float* Ws = sm;                     // F_IN * F_OUT = 32768 floats
    float* xs = sm + F_IN * F_OUT;      // ROWS_PER_BLK * F_IN = 8192 floats
    __shared__ float e1s[ROWS_PER_BLK];
    __shared__ float e2s[ROWS_PER_BLK];

    const int tid = threadIdx.x;
    const int row0 = blockIdx.x * ROWS_PER_BLK;

    // stage W and the x tile
    #pragma unroll 4
    for (int i = tid; i < F_IN * F_OUT; i += 256) Ws[i] = W[i];
    #pragma unroll 4
    for (int i = tid; i < ROWS_PER_BLK * F_IN; i += 256)
        xs[i] = x[(size_t)row0 * F_IN + i];
    __syncthreads();

    const int cg = tid & 31;            // 32 col groups of 4
    const int rg = tid >> 5;            // 8 row groups of 4 (== warp id)
    const int c0 = cg * 4;
    const int r0 = rg * 4;

    float acc[4][4];
    #pragma unroll
    for (int i = 0; i < 4; i++)
        #pragma unroll
        for (int j = 0; j < 4; j++) acc[i][j] = 0.0f;

    #pragma unroll 4
    for (int k = 0; k < F_IN; k++) {
        float4 wv = *reinterpret_cast<const float4*>(&Ws[k * F_OUT + c0]);
        float xr0 = xs[(r0 + 0) * F_IN + k];
        float xr1 = xs[(r0 + 1) * F_IN + k];
        float xr2 = xs[(r0 + 2) * F_IN + k];
        float xr3 = xs[(r0 + 3) * F_IN + k];
        acc[0][0] += xr0 * wv.x; acc[0][1] += xr0 * wv.y; acc[0][2] += xr0 * wv.z; acc[0][3] += xr0 * wv.w;
        acc[1][0] += xr1 * wv.x; acc[1][1] += xr1 * wv.y; acc[1][2] += xr1 * wv.z; acc[1][3] += xr1 * wv.w;
        acc[2][0] += xr2 * wv.x; acc[2][1] += xr2 * wv.y; acc[2][2] += xr2 * wv.z; acc[2][3] += xr2 * wv.w;
        acc[3][0] += xr3 * wv.x; acc[3][1] += xr3 * wv.y; acc[3][2] += xr3 * wv.z; acc[3][3] += xr3 * wv.w;
    }

    // write h
    #pragma unroll
    for (int i = 0; i < 4; i++) {
        float4 v = make_float4(acc[i][0], acc[i][1], acc[i][2], acc[i][3]);
        *reinterpret_cast<float4*>(&g_h[(size_t)(row0 + r0 + i) * F_OUT + c0]) = v;
    }

    // fused e1/e2: each warp exclusively owns rows r0..r0+3 across all 128 cols
    float a1v[4], a2v[4];
    #pragma unroll
    for (int j = 0; j < 4; j++) { a1v[j] = a[c0 + j]; a2v[j] = a[F_OUT + c0 + j]; }

    #pragma unroll
    for (int i = 0; i < 4; i++) {
        float p1 = acc[i][0]*a1v[0] + acc[i][1]*a1v[1] + acc[i][2]*a1v[2] + acc[i][3]*a1v[3];
        float p2 = acc[i][0]*a2v[0] + acc[i][1]*a2v[1] + acc[i][2]*a2v[2] + acc[i][3]*a2v[3];
        #pragma unroll
        for (int o = 16; o; o >>= 1) {
            p1 += __shfl_xor_sync(0xffffffffu, p1, o);
            p2 += __shfl_xor_sync(0xffffffffu, p2, o);
        }
        if (cg == 0) { e1s[r0 + i] = p1; e2s[r0 + i] = p2; }
    }
    __syncthreads();
    if (tid < ROWS_PER_BLK) {
        g_e1[row0 + tid] = e1s[tid];
        g_e2[row0 + tid] = e2s[tid];
    }
}

// ---------------------------------------------------------------------------
// K2: per row — stream adj row, compact nonzeros, online softmax, gather h.
// grid = 8192 blocks, 256 threads.
// ---------------------------------------------------------------------------
__global__ void __launch_bounds__(256)
gat_k2(const float* __restrict__ adj, float* __restrict__ out)
{
    const int row = blockIdx.x;
    const int tid = threadIdx.x;

    __shared__ unsigned short idxs[MAXNZ];
    __shared__ float vals[MAXNZ];
    __shared__ int cnt;
    __shared__ float red[32];
    __shared__ float m_sh, s_sh;
    __shared__ float acc_sh[256];

    if (tid == 0) cnt = 0;
    __syncthreads();

    const float e1i = g_e1[row];
    const float4* arow = reinterpret_cast<const float4*>(adj + (size_t)row * N_NODES);

    float lmax = -INFINITY;
    #pragma unroll
    for (int it = 0; it < 8; it++) {
        int q = it * 256 + tid;             // float4 index within the row
        float4 v = arow[q];
        int j0 = q * 4;
        if (v.x > 0.0f) {
            float e = e1i + g_e2[j0 + 0]; e = e > 0.0f ? e : ALPHA * e;
            int p = atomicAdd(&cnt, 1); if (p < MAXNZ) { idxs[p] = (unsigned short)(j0 + 0); vals[p] = e; }
            lmax = fmaxf(lmax, e);
        }
        if (v.y > 0.0f) {
            float e = e1i + g_e2[j0 + 1]; e = e > 0.0f ? e : ALPHA * e;
            int p = atomicAdd(&cnt, 1); if (p < MAXNZ) { idxs[p] = (unsigned short)(j0 + 1); vals[p] = e; }
            lmax = fmaxf(lmax, e);
        }
        if (v.z > 0.0f) {
            float e = e1i + g_e2[j0 + 2]; e = e > 0.0f ? e : ALPHA * e;
            int p = atomicAdd(&cnt, 1); if (p < MAXNZ) { idxs[p] = (unsigned short)(j0 + 2); vals[p] = e; }
            lmax = fmaxf(lmax, e);
        }
        if (v.w > 0.0f) {
            float e = e1i + g_e2[j0 + 3]; e = e > 0.0f ? e : ALPHA * e;
            int p = atomicAdd(&cnt, 1); if (p < MAXNZ) { idxs[p] = (unsigned short)(j0 + 3); vals[p] = e; }
            lmax = fmaxf(lmax, e);
        }
    }

    // block max reduction
    #pragma unroll
    for (int o = 16; o; o >>= 1) lmax = fmaxf(lmax, __shfl_xor_sync(0xffffffffu, lmax, o));
    if ((tid & 31) == 0) red[tid >> 5] = lmax;
    __syncthreads();
    if (tid == 0) {
        float t = red[0];
        #pragma unroll
        for (int w = 1; w < 8; w++) t = fmaxf(t, red[w]);
        m_sh = t;
    }
    __syncthreads();

    const float m = m_sh;
    const int n = (cnt < MAXNZ) ? cnt : MAXNZ;

    // exponentiate + sum
    float ls = 0.0f;
    for (int k = tid; k < n; k += 256) {
        float ev = __expf(vals[k] - m);
        vals[k] = ev;
        ls += ev;
    }
    #pragma unroll
    for (int o = 16; o; o >>= 1) ls += __shfl_xor_sync(0xffffffffu, ls, o);
    if ((tid & 31) == 0) red[tid >> 5] = ls;
    __syncthreads();
    if (tid == 0) {
        float t = 0.0f;
        #pragma unroll
        for (int w = 0; w < 8; w++) t += red[w];
        s_sh = t;
    }
    __syncthreads();

    const float inv = 1.0f / s_sh;

    // gather: 2 halves x 128 columns
    const int c = tid & 127;
    const int half = tid >> 7;
    float acc = 0.0f;
    for (int k = half; k < n; k += 2)
        acc += vals[k] * g_h[(size_t)idxs[k] * F_OUT + c];
    acc_sh[tid] = acc;
    __syncthreads();

    if (tid < 128) {
        float r = (acc_sh[tid] + acc_sh[tid + 128]) * inv;
        out[(size_t)row * F_OUT + tid] = r > 0.0f ? r : expm1f(r);
    }
}

// ---------------------------------------------------------------------------
extern "C" void kernel_launch(void* const* d_in, const int* in_sizes, int n_in,
                              void* d_out, int out_size)
{
    const float* x   = (const float*)d_in[0];
    const float* adj = (const float*)d_in[1];
    const float* W   = (const float*)d_in[2];
    const float* a   = (const float*)d_in[3];
    float* out = (float*)d_out;

    const int smem1 = (F_IN * F_OUT + ROWS_PER_BLK * F_IN) * sizeof(float); // 160 KB
    static bool attr_set = false;
    if (!attr_set) {
        cudaFuncSetAttribute(gat_k1, cudaFuncAttributeMaxDynamicSharedMemorySize, smem1);
        attr_set = true;
    }

    gat_k1<<<N_NODES / ROWS_PER_BLK, 256, smem1>>>(x, W, a);
    gat_k2<<<N_NODES, 256>>>(adj, out);
}

// round 3
// speedup vs baseline: 1.1335x; 1.1335x over previous
#include <cuda_runtime.h>
#include <math.h>

#define N_NODES 8192
#define F_IN 256
#define F_OUT 128
#define ALPHA 0.2f
#define MAXNZ 1024

#define BM 32
#define BK 64

// Scratch (no allocations allowed)
__device__ float g_h[N_NODES * F_OUT];   // 4 MB
__device__ float g_e1[N_NODES];
__device__ float g_e2[N_NODES];

// ---------------------------------------------------------------------------
// K1: h = x @ W  (k-tiled, BM=32 x BN=128 x BK=64), fused e1=h@a1, e2=h@a2.
// grid = 256 blocks, 256 threads, static smem = 40KB -> multiple CTAs/SM.
// ---------------------------------------------------------------------------
__global__ void __launch_bounds__(256)
gat_k1(const float* __restrict__ x, const float* __restrict__ W,
       const float* __restrict__ a)
{
    __shared__ __align__(16) float xs[BM * BK];        // 8 KB
    __shared__ __align__(16) float Ws[BK * F_OUT];     // 32 KB
    __shared__ float e1s[BM];
    __shared__ float e2s[BM];

    const int tid = threadIdx.x;
    const int row0 = blockIdx.x * BM;

    const int cg = tid & 31;             // 32 col groups of 4
    const int rg = tid >> 5;             // 8 row groups of 4 (== warp id)
    const int c0 = cg * 4;
    const int r0 = rg * 4;

    float acc[4][4];
    #pragma unroll
    for (int i = 0; i < 4; i++)
        #pragma unroll
        for (int j = 0; j < 4; j++) acc[i][j] = 0.0f;

    for (int k0 = 0; k0 < F_IN; k0 += BK) {
        // stage x tile: 32 rows x 64 cols = 512 float4, 2 per thread
        #pragma unroll
        for (int t = 0; t < 2; t++) {
            int idx = t * 256 + tid;              // float4 index into xs
            int r = idx >> 4;                     // 64/4 = 16 float4 per row
            int c = (idx & 15) * 4;
            *reinterpret_cast<float4*>(&xs[r * BK + c]) =
                *reinterpret_cast<const float4*>(&x[(size_t)(row0 + r) * F_IN + k0 + c]);
        }
        // stage W tile: 64 rows x 128 cols = 2048 float4, 8 per thread
        #pragma unroll
        for (int t = 0; t < 8; t++) {
            int idx = t * 256 + tid;
            *reinterpret_cast<float4*>(&Ws[idx * 4]) =
                *reinterpret_cast<const float4*>(&W[(size_t)(k0) * F_OUT + idx * 4]);
        }
        __syncthreads();

        #pragma unroll 8
        for (int k = 0; k < BK; k++) {
            float4 wv = *reinterpret_cast<const float4*>(&Ws[k * F_OUT + c0]);
            float xr0 = xs[(r0 + 0) * BK + k];
            float xr1 = xs[(r0 + 1) * BK + k];
            float xr2 = xs[(r0 + 2) * BK + k];
            float xr3 = xs[(r0 + 3) * BK + k];
            acc[0][0] += xr0 * wv.x; acc[0][1] += xr0 * wv.y; acc[0][2] += xr0 * wv.z; acc[0][3] += xr0 * wv.w;
            acc[1][0] += xr1 * wv.x; acc[1][1] += xr1 * wv.y; acc[1][2] += xr1 * wv.z; acc[1][3] += xr1 * wv.w;
            acc[2][0] += xr2 * wv.x; acc[2][1] += xr2 * wv.y; acc[2][2] += xr2 * wv.z; acc[2][3] += xr2 * wv.w;
            acc[3][0] += xr3 * wv.x; acc[3][1] += xr3 * wv.y; acc[3][2] += xr3 * wv.z; acc[3][3] += xr3 * wv.w;
        }
        __syncthreads();
    }

    // write h
    #pragma unroll
    for (int i = 0; i < 4; i++) {
        float4 v = make_float4(acc[i][0], acc[i][1], acc[i][2], acc[i][3]);
        *reinterpret_cast<float4*>(&g_h[(size_t)(row0 + r0 + i) * F_OUT + c0]) = v;
    }

    // fused e1/e2: warp rg owns rows r0..r0+3 across all 128 cols
    float a1v[4], a2v[4];
    #pragma unroll
    for (int j = 0; j < 4; j++) { a1v[j] = a[c0 + j]; a2v[j] = a[F_OUT + c0 + j]; }

    #pragma unroll
    for (int i = 0; i < 4; i++) {
        float p1 = acc[i][0]*a1v[0] + acc[i][1]*a1v[1] + acc[i][2]*a1v[2] + acc[i][3]*a1v[3];
        float p2 = acc[i][0]*a2v[0] + acc[i][1]*a2v[1] + acc[i][2]*a2v[2] + acc[i][3]*a2v[3];
        #pragma unroll
        for (int o = 16; o; o >>= 1) {
            p1 += __shfl_xor_sync(0xffffffffu, p1, o);
            p2 += __shfl_xor_sync(0xffffffffu, p2, o);
        }
        if (cg == 0) { e1s[r0 + i] = p1; e2s[r0 + i] = p2; }
    }
    __syncthreads();
    if (tid < BM) {
        g_e1[row0 + tid] = e1s[tid];
        g_e2[row0 + tid] = e2s[tid];
    }
}

// ---------------------------------------------------------------------------
// K2: per row — stream adj (MLP=8 prefetch), ballot-compact nonzeros,
// max via monotone leakyrelu shortcut, fused exp+gather with float4 loads.
// grid = 8192 blocks, 256 threads.
// ---------------------------------------------------------------------------
__global__ void __launch_bounds__(256)
gat_k2(const float* __restrict__ adj, float* __restrict__ out)
{
    const int row = blockIdx.x;
    const int tid = threadIdx.x;
    const int lane = tid & 31;
    const int wid = tid >> 5;

    __shared__ unsigned short idxs[MAXNZ];
    __shared__ float e2s[MAXNZ];
    __shared__ int cnt;
    __shared__ float red[8];
    __shared__ float m_sh;
    __shared__ float warp_ls[8];
    __shared__ __align__(16) float warp_acc[8][128];   // 4 KB

    if (tid == 0) cnt = 0;
    __syncthreads();

    const float e1i = g_e1[row];
    const float4* arow = reinterpret_cast<const float4*>(adj + (size_t)row * N_NODES);

    // prefetch the whole adj row slice for this thread (MLP = 8)
    float4 v[8];
    #pragma unroll
    for (int it = 0; it < 8; it++) v[it] = arow[it * 256 + tid];

    float lmax2 = -INFINITY;   // max of e2[j] over this thread's nonzeros
    #pragma unroll
    for (int it = 0; it < 8; it++) {
        const int j0 = (it * 256 + tid) * 4;
        const float vc[4] = {v[it].x, v[it].y, v[it].z, v[it].w};
        #pragma unroll
        for (int c = 0; c < 4; c++) {
            const bool nz = vc[c] > 0.0f;
            const unsigned b = __ballot_sync(0xffffffffu, nz);
            if (b) {
                int base;
                if (lane == 0) base = atomicAdd(&cnt, __popc(b));
                base = __shfl_sync(0xffffffffu, base, 0);
                if (nz) {
                    int pos = base + __popc(b & ((1u << lane) - 1u));
                    if (pos < MAXNZ) {
                        float e2v = g_e2[j0 + c];
                        idxs[pos] = (unsigned short)(j0 + c);
                        e2s[pos] = e2v;
                        lmax2 = fmaxf(lmax2, e2v);
                    }
                }
            }
        }
    }

    // block max of e2 -> global max of e = lrelu(e1i + e2) by monotonicity
    #pragma unroll
    for (int o = 16; o; o >>= 1) lmax2 = fmaxf(lmax2, __shfl_xor_sync(0xffffffffu, lmax2, o));
    if (lane == 0) red[wid] = lmax2;
    __syncthreads();
    if (tid == 0) {
        float t = red[0];
        #pragma unroll
        for (int w = 1; w < 8; w++) t = fmaxf(t, red[w]);
        float M = e1i + t;
        m_sh = M > 0.0f ? M : ALPHA * M;
    }
    __syncthreads();

    const float M = m_sh;
    const int n = (cnt < MAXNZ) ? cnt : MAXNZ;

    // fused exp + gather: warp wid handles k = wid, wid+8, ...; lane covers 4 cols
    float acc0 = 0.0f, acc1 = 0.0f, acc2 = 0.0f, acc3 = 0.0f;
    float ls = 0.0f;
    for (int k = wid; k < n; k += 8) {
        float e = e1i + e2s[k];
        e = e > 0.0f ? e : ALPHA * e;
        const float p = __expf(e - M);
        const float4 hv = *reinterpret_cast<const float4*>(
            &g_h[(size_t)idxs[k] * F_OUT + lane * 4]);
        acc0 += p * hv.x; acc1 += p * hv.y; acc2 += p * hv.z; acc3 += p * hv.w;
        ls += p;
    }
    if (lane == 0) warp_ls[wid] = ls;   // all lanes of a warp hold identical ls
    *reinterpret_cast<float4*>(&warp_acc[wid][lane * 4]) = make_float4(acc0, acc1, acc2, acc3);
    __syncthreads();

    if (tid < 128) {
        float s = 0.0f;
        #pragma unroll
        for (int w = 0; w < 8; w++) s += warp_ls[w];
        float r = 0.0f;
        #pragma unroll
        for (int w = 0; w < 8; w++) r += warp_acc[w][tid];
        r /= s;
        out[(size_t)row * F_OUT + tid] = r > 0.0f ? r : expm1f(r);
    }
}

// ---------------------------------------------------------------------------
extern "C" void kernel_launch(void* const* d_in, const int* in_sizes, int n_in,
                              void* d_out, int out_size)
{
    const float* x   = (const float*)d_in[0];
    const float* adj = (const float*)d_in[1];
    const float* W   = (const float*)d_in[2];
    const float* a   = (const float*)d_in[3];
    float* out = (float*)d_out;

    gat_k1<<<N_NODES / BM, 256>>>(x, W, a);
    gat_k2<<<N_NODES, 256>>>(adj, out);
}

// round 4
// speedup vs baseline: 1.6204x; 1.4295x over previous
#include <cuda_runtime.h>
#include <cuda_fp16.h>
#include <math.h>

#define N_NODES 8192
#define F_IN 256
#define F_OUT 128
#define ALPHA 0.2f
#define MAXNZ 1024

#define BM 32
#define BK 64

// Scratch (no allocations allowed)
__device__ __half2 g_h2[N_NODES * F_OUT / 2];   // 2 MB, h in fp16
__device__ float g_e1[N_NODES];
__device__ float g_e2[N_NODES];

// ---------------------------------------------------------------------------
// K1: h = x @ W  (k-tiled, BM=32 x BN=128 x BK=64), fused e1=h@a1, e2=h@a2.
// h stored as fp16 (gather bandwidth), e1/e2 from fp32 accumulators.
// ---------------------------------------------------------------------------
__global__ void __launch_bounds__(256)
gat_k1(const float* __restrict__ x, const float* __restrict__ W,
       const float* __restrict__ a)
{
    __shared__ __align__(16) float xs[BM * BK];        // 8 KB
    __shared__ __align__(16) float Ws[BK * F_OUT];     // 32 KB
    __shared__ float e1s[BM];
    __shared__ float e2s[BM];

    const int tid = threadIdx.x;
    const int row0 = blockIdx.x * BM;

    const int cg = tid & 31;             // 32 col groups of 4
    const int rg = tid >> 5;             // 8 row groups of 4 (== warp id)
    const int c0 = cg * 4;
    const int r0 = rg * 4;

    float acc[4][4];
    #pragma unroll
    for (int i = 0; i < 4; i++)
        #pragma unroll
        for (int j = 0; j < 4; j++) acc[i][j] = 0.0f;

    for (int k0 = 0; k0 < F_IN; k0 += BK) {
        #pragma unroll
        for (int t = 0; t < 2; t++) {
            int idx = t * 256 + tid;
            int r = idx >> 4;
            int c = (idx & 15) * 4;
            *reinterpret_cast<float4*>(&xs[r * BK + c]) =
                *reinterpret_cast<const float4*>(&x[(size_t)(row0 + r) * F_IN + k0 + c]);
        }
        #pragma unroll
        for (int t = 0; t < 8; t++) {
            int idx = t * 256 + tid;
            *reinterpret_cast<float4*>(&Ws[idx * 4]) =
                *reinterpret_cast<const float4*>(&W[(size_t)(k0) * F_OUT + idx * 4]);
        }
        __syncthreads();

        #pragma unroll 8
        for (int k = 0; k < BK; k++) {
            float4 wv = *reinterpret_cast<const float4*>(&Ws[k * F_OUT + c0]);
            float xr0 = xs[(r0 + 0) * BK + k];
            float xr1 = xs[(r0 + 1) * BK + k];
            float xr2 = xs[(r0 + 2) * BK + k];
            float xr3 = xs[(r0 + 3) * BK + k];
            acc[0][0] += xr0 * wv.x; acc[0][1] += xr0 * wv.y; acc[0][2] += xr0 * wv.z; acc[0][3] += xr0 * wv.w;
            acc[1][0] += xr1 * wv.x; acc[1][1] += xr1 * wv.y; acc[1][2] += xr1 * wv.z; acc[1][3] += xr1 * wv.w;
            acc[2][0] += xr2 * wv.x; acc[2][1] += xr2 * wv.y; acc[2][2] += xr2 * wv.z; acc[2][3] += xr2 * wv.w;
            acc[3][0] += xr3 * wv.x; acc[3][1] += xr3 * wv.y; acc[3][2] += xr3 * wv.z; acc[3][3] += xr3 * wv.w;
        }
        __syncthreads();
    }

    // write h as fp16 (half2 pairs): row r, cols c0..c0+3 -> 2 half2 = 8B
    #pragma unroll
    for (int i = 0; i < 4; i++) {
        __half2 ha = __floats2half2_rn(acc[i][0], acc[i][1]);
        __half2 hb = __floats2half2_rn(acc[i][2], acc[i][3]);
        __half2* dst = &g_h2[(size_t)(row0 + r0 + i) * (F_OUT / 2) + (c0 >> 1)];
        uint2 u;
        u.x = *reinterpret_cast<unsigned*>(&ha);
        u.y = *reinterpret_cast<unsigned*>(&hb);
        *reinterpret_cast<uint2*>(dst) = u;
    }

    // fused e1/e2 from fp32 accumulators
    float a1v[4], a2v[4];
    #pragma unroll
    for (int j = 0; j < 4; j++) { a1v[j] = a[c0 + j]; a2v[j] = a[F_OUT + c0 + j]; }

    #pragma unroll
    for (int i = 0; i < 4; i++) {
        float p1 = acc[i][0]*a1v[0] + acc[i][1]*a1v[1] + acc[i][2]*a1v[2] + acc[i][3]*a1v[3];
        float p2 = acc[i][0]*a2v[0] + acc[i][1]*a2v[1] + acc[i][2]*a2v[2] + acc[i][3]*a2v[3];
        #pragma unroll
        for (int o = 16; o; o >>= 1) {
            p1 += __shfl_xor_sync(0xffffffffu, p1, o);
            p2 += __shfl_xor_sync(0xffffffffu, p2, o);
        }
        if (cg == 0) { e1s[r0 + i] = p1; e2s[r0 + i] = p2; }
    }
    __syncthreads();
    if (tid < BM) {
        g_e1[row0 + tid] = e1s[tid];
        g_e2[row0 + tid] = e2s[tid];
    }
}

// ---------------------------------------------------------------------------
// K2: per row — stream adj (MLP=8), UNORDERED per-thread compaction
// (1 shared atomic per thread), coalesced e2 pass + max, fused exp + fp16
// h gather. grid = 8192 blocks, 256 threads.
// ---------------------------------------------------------------------------
__global__ void __launch_bounds__(256)
gat_k2(const float* __restrict__ adj, float* __restrict__ out)
{
    const int row = blockIdx.x;
    const int tid = threadIdx.x;
    const int lane = tid & 31;
    const int wid = tid >> 5;

    __shared__ unsigned short idxs[MAXNZ];
    __shared__ float e2s[MAXNZ];
    __shared__ int cnt;
    __shared__ float red[8];
    __shared__ float m_sh;
    __shared__ float warp_ls[8];
    __shared__ __align__(16) float warp_acc[8][128];

    if (tid == 0) cnt = 0;
    __syncthreads();

    const float e1i = g_e1[row];
    const float4* arow = reinterpret_cast<const float4*>(adj + (size_t)row * N_NODES);

    // stream this thread's slice of the adj row (MLP = 8)
    float4 v[8];
    #pragma unroll
    for (int it = 0; it < 8; it++) v[it] = arow[it * 256 + tid];

    // build per-thread nonzero bitmask (bit = it*4 + component)
    unsigned mask = 0;
    #pragma unroll
    for (int it = 0; it < 8; it++) {
        mask |= (v[it].x > 0.0f ? 1u : 0u) << (it * 4 + 0);
        mask |= (v[it].y > 0.0f ? 1u : 0u) << (it * 4 + 1);
        mask |= (v[it].z > 0.0f ? 1u : 0u) << (it * 4 + 2);
        mask |= (v[it].w > 0.0f ? 1u : 0u) << (it * 4 + 3);
    }
    int myc = __popc(mask);
    int base = 0;
    if (myc) base = atomicAdd(&cnt, myc);   // unordered compaction: 1 atomic/thread
    while (mask) {
        int b = __ffs(mask) - 1;
        mask &= mask - 1;
        int j = ((b >> 2) * 256 + tid) * 4 + (b & 3);
        if (base < MAXNZ) idxs[base] = (unsigned short)j;
        base++;
    }
    __syncthreads();

    const int n = (cnt < MAXNZ) ? cnt : MAXNZ;

    // coalesced e2 pass + block max (lrelu monotone -> shortcut)
    float lmax2 = -INFINITY;
    for (int k = tid; k < n; k += 256) {
        float e2v = g_e2[idxs[k]];
        e2s[k] = e2v;
        lmax2 = fmaxf(lmax2, e2v);
    }
    #pragma unroll
    for (int o = 16; o; o >>= 1) lmax2 = fmaxf(lmax2, __shfl_xor_sync(0xffffffffu, lmax2, o));
    if (lane == 0) red[wid] = lmax2;
    __syncthreads();
    if (tid == 0) {
        float t = red[0];
        #pragma unroll
        for (int w = 1; w < 8; w++) t = fmaxf(t, red[w]);
        float M = e1i + t;
        m_sh = M > 0.0f ? M : ALPHA * M;
    }
    __syncthreads();

    const float M = m_sh;

    // fused exp + fp16 gather: warp wid handles k = wid, wid+8, ...
    // lane covers cols [lane*4, lane*4+4) as 2 half2 (8B load)
    float acc0 = 0.0f, acc1 = 0.0f, acc2 = 0.0f, acc3 = 0.0f;
    float ls = 0.0f;
    for (int k = wid; k < n; k += 8) {
        float e = e1i + e2s[k];
        e = e > 0.0f ? e : ALPHA * e;
        const float p = __expf(e - M);
        uint2 u = *reinterpret_cast<const uint2*>(
            &g_h2[(size_t)idxs[k] * (F_OUT / 2) + lane * 2]);
        __half2 ha = *reinterpret_cast<__half2*>(&u.x);
        __half2 hb = *reinterpret_cast<__half2*>(&u.y);
        float2 fa = __half22float2(ha);
        float2 fb = __half22float2(hb);
        acc0 += p * fa.x; acc1 += p * fa.y; acc2 += p * fb.x; acc3 += p * fb.y;
        ls += p;
    }
    if (lane == 0) warp_ls[wid] = ls;
    *reinterpret_cast<float4*>(&warp_acc[wid][lane * 4]) = make_float4(acc0, acc1, acc2, acc3);
    __syncthreads();

    if (tid < 128) {
        float s = 0.0f;
        #pragma unroll
        for (int w = 0; w < 8; w++) s += warp_ls[w];
        float r = 0.0f;
        #pragma unroll
        for (int w = 0; w < 8; w++) r += warp_acc[w][tid];
        r /= s;
        out[(size_t)row * F_OUT + tid] = r > 0.0f ? r : expm1f(r);
    }
}

// ---------------------------------------------------------------------------
extern "C" void kernel_launch(void* const* d_in, const int* in_sizes, int n_in,
                              void* d_out, int out_size)
{
    const float* x   = (const float*)d_in[0];
    const float* adj = (const float*)d_in[1];
    const float* W   = (const float*)d_in[2];
    const float* a   = (const float*)d_in[3];
    float* out = (float*)d_out;

    gat_k1<<<N_NODES / BM, 256>>>(x, W, a);
    gat_k2<<<N_NODES, 256>>>(adj, out);
}